// round 11
// baseline (speedup 1.0000x reference)
#include <cuda_runtime.h>

// SerialResnet as a tabulated 1-D function; 64 KB center table in SMEM
// (2 CTAs/SM, 64 warps), gaussian tails (0.115%) from L2, software-pipelined
// x prefetch. Build overlapped via PDL.
//
// Raw grid: 2^15 intervals over [-6.5, 6.5]; center = raw[NT .. NT+NC]
// covers [-3.25, 3.25) with identical step -> rel_err == single-table 2^15.

#define NL 20
#define LOG2_NINT 15
#define N_INT (1 << LOG2_NINT)          // 32768 intervals over [-6.5, 6.5]
#define XLO (-6.5f)
#define XRANGE 13.0f

#define NT (N_INT / 4)                  // 8192: center starts at raw[NT]
#define NC (N_INT / 2)                  // 16384 center intervals
#define SCALE ((float)N_INT / XRANGE)   // 1/dx

#define EVAL_THREADS 1024
#define SMEM_BYTES ((NC + 1) * 4 + 16)  // ~64 KB -> 2 CTAs/SM

__device__ float g_rawtab[N_INT + 1];   // F at grid points (L2-resident)

__device__ __forceinline__ float tanh_f32(float v) {
    float y;
    asm("tanh.approx.f32 %0, %1;" : "=f"(y) : "f"(v));
    return y;
}

// ---------------------------------------------------------------- build ----
__global__ __launch_bounds__(256)
void build_table_kernel(const float* __restrict__ W, const float* __restrict__ b) {
    asm volatile("griddepcontrol.launch_dependents;");

    const int i = blockIdx.x * blockDim.x + threadIdx.x;
    if (i > N_INT) return;

    const float xi = XLO + (float)i * (XRANGE / (float)N_INT);
    float h0 = xi, h1 = xi;

#pragma unroll
    for (int l = 0; l < NL; ++l) {
        const float4 wl = __ldg(reinterpret_cast<const float4*>(W) + l);
        const float2 bl = __ldg(reinterpret_cast<const float2*>(b) + l);
        const float z0 = fmaf(wl.x, h0, fmaf(wl.y, h1, bl.x));
        const float z1 = fmaf(wl.z, h0, fmaf(wl.w, h1, bl.y));
        h0 += tanh_f32(z0);
        h1 += tanh_f32(z1);
    }
    g_rawtab[i] = 0.5f * (h0 + h1);
}

// ----------------------------------------------------------------- eval ----
__device__ __forceinline__ float interp1(const float* __restrict__ s_tab, float xv) {
    // Center: i in [0, NC) iff x in [-3.25, 3.25). s_tab[i] == raw[NT+i].
    const float idxf = fmaf(xv, SCALE, 3.25f * SCALE);
    const int i = __float2int_rd(idxf);
    if ((unsigned)i < (unsigned)NC) {
        const float frac = idxf - (float)i;
        const float f0 = s_tab[i];
        const float f1 = s_tab[i + 1];
        return fmaf(frac, f1 - f0, f0);
    }
    // Tail (~0.115% of elements): interpolate from L2-resident raw table.
    const float gf = fmaf(xv, SCALE, 6.5f * SCALE);
    int gi = __float2int_rd(gf);
    gi = max(0, min(gi, N_INT - 1));
    const float frac = gf - (float)gi;
    const float f0 = __ldg(&g_rawtab[gi]);
    const float f1 = __ldg(&g_rawtab[gi + 1]);
    return fmaf(frac, f1 - f0, f0);
}

__global__ __launch_bounds__(EVAL_THREADS, 2)
void eval_kernel(const float* __restrict__ x, float* __restrict__ out, int n) {
    extern __shared__ float s_tab[];

    const int tid = threadIdx.x;
    const float4* __restrict__ x4 = reinterpret_cast<const float4*>(x);
    float4* __restrict__ o4 = reinterpret_cast<float4*>(out);

    const int ngroups = n >> 2;
    const int stride = gridDim.x * EVAL_THREADS;

    int g = blockIdx.x * EVAL_THREADS + tid;

    // Prologue x load: independent of the table -> issue before the PDL wait.
    float4 cur;
    bool v = g < ngroups;
    if (v) cur = x4[g];

    asm volatile("griddepcontrol.wait;" ::: "memory");

    // Stage center table: raw[NT .. NT+NC] -> s_tab[0 .. NC].
    {
        const float4* src = reinterpret_cast<const float4*>(g_rawtab + NT);
        float4* dst = reinterpret_cast<float4*>(s_tab);
#pragma unroll
        for (int j = 0; j < (NC / 4) / EVAL_THREADS; ++j) {
            const int k = j * EVAL_THREADS + tid;
            dst[k] = src[k];
        }
        if (tid == 0) s_tab[NC] = g_rawtab[NT + NC];
    }
    __syncthreads();

    while (v) {
        const int gn = g + stride;
        const bool vn = gn < ngroups;
        float4 nxt;
        if (vn) nxt = x4[gn];        // prefetch before computing current

        float4 ov;
        ov.x = interp1(s_tab, cur.x);
        ov.y = interp1(s_tab, cur.y);
        ov.z = interp1(s_tab, cur.z);
        ov.w = interp1(s_tab, cur.w);
        o4[g] = ov;

        cur = nxt;
        g = gn;
        v = vn;
    }

    // Tail (n % 4 != 0): block 0.
    if (blockIdx.x == 0) {
        for (int i1 = (n & ~3) + tid; i1 < n; i1 += EVAL_THREADS) {
            out[i1] = interp1(s_tab, x[i1]);
        }
    }
}

extern "C" void kernel_launch(void* const* d_in, const int* in_sizes, int n_in,
                              void* d_out, int out_size) {
    const float* x = (const float*)d_in[0];
    const float* W = (const float*)d_in[1];
    const float* b = (const float*)d_in[2];
    float* out = (float*)d_out;

    const int n = in_sizes[0];

    static int n_sm = 0;
    static bool attr_set = false;
    if (!attr_set) {
        cudaDeviceGetAttribute(&n_sm, cudaDevAttrMultiProcessorCount, 0);
        if (n_sm <= 0) n_sm = 148;
        cudaFuncSetAttribute(eval_kernel,
                             cudaFuncAttributeMaxDynamicSharedMemorySize,
                             SMEM_BYTES);
        attr_set = true;
    }

    build_table_kernel<<<(N_INT + 1 + 255) / 256, 256>>>(W, b);

    cudaLaunchConfig_t cfg = {};
    cfg.gridDim = dim3(2 * n_sm, 1, 1);      // 2 CTAs per SM
    cfg.blockDim = dim3(EVAL_THREADS, 1, 1);
    cfg.dynamicSmemBytes = SMEM_BYTES;
    cfg.stream = 0;
    cudaLaunchAttribute at[1];
    at[0].id = cudaLaunchAttributeProgrammaticStreamSerialization;
    at[0].val.programmaticStreamSerializationAllowed = 1;
    cfg.attrs = at;
    cfg.numAttrs = 1;
    cudaLaunchKernelEx(&cfg, eval_kernel, x, out, n);
}